// round 1
// baseline (speedup 1.0000x reference)
#include <cuda_runtime.h>
#include <math.h>

#define PH 512
#define PW 512
#define NCH 32
#define HIDDEN 128
#define ALPHA 1e-4f
#define MAX_CAMS 4096
#define CPB 8   // cameras per block in kernel 1

// Per-camera final 4x4 matrices (row-major), 16B-aligned for float4 access.
__device__ float4 g_table[MAX_CAMS * 4];

__device__ __forceinline__ float silu_f(float x) {
    return x / (1.0f + expf(-x));
}

__device__ __forceinline__ float bilerp_border(const float* __restrict__ plane,
                                               int ch, float cx, float cy) {
    // align_corners=True, padding_mode='border', matches reference fp32 math
    float x = (cx + 1.0f) * 0.5f * (float)(PW - 1);
    float y = (cy + 1.0f) * 0.5f * (float)(PH - 1);
    float x0f = floorf(x), y0f = floorf(y);
    float wx = x - x0f, wy = y - y0f;
    int x0 = min(max((int)x0f, 0), PW - 1);
    int x1 = min(max((int)x0f + 1, 0), PW - 1);
    int y0 = min(max((int)y0f, 0), PH - 1);
    int y1 = min(max((int)y0f + 1, 0), PH - 1);
    const float* pc = plane + (size_t)ch * (PH * PW);
    float v00 = __ldg(pc + y0 * PW + x0);
    float v01 = __ldg(pc + y0 * PW + x1);
    float v10 = __ldg(pc + y1 * PW + x0);
    float v11 = __ldg(pc + y1 * PW + x1);
    return v00 * (1.0f - wx) * (1.0f - wy)
         + v01 * wx * (1.0f - wy)
         + v10 * (1.0f - wx) * wy
         + v11 * wx * wy;
}

__global__ void __launch_bounds__(128) cam_kernel(
    const float* __restrict__ t,
    const float* __restrict__ pxy,
    const float* __restrict__ pxz,
    const float* __restrict__ pyz,
    const float* __restrict__ w1, const float* __restrict__ b1,
    const float* __restrict__ w2, const float* __restrict__ b2,
    const float* __restrict__ w3, const float* __restrict__ b3,
    const float* __restrict__ init_c2w,
    int num_cams)
{
    int cam0 = blockIdx.x * CPB;
    int tid = threadIdx.x;

    __shared__ float s_ts[CPB][4];
    __shared__ float s_codes[CPB][96];
    __shared__ float s_h1[CPB][HIDDEN];
    __shared__ float s_h2[CPB][HIDDEN];
    __shared__ float s_rot[CPB][3];

    if (tid < CPB * 3) {
        int c = tid / 3, a = tid % 3;
        int cam = cam0 + c;
        s_ts[c][a] = (cam < num_cams) ? t[cam * 3 + a] : 0.0f;
    }
    __syncthreads();

    // Tri-plane sampling: CPB*96 = 768 tasks over 128 threads.
    // codes layout per cam: [0:32) xy, [32:64) xz, [64:96) yz  (AXES (0,1),(0,2),(1,2))
    for (int task = tid; task < CPB * 96; task += 128) {
        int c = task / 96;
        int code = task % 96;
        int p = code >> 5;
        int ch = code & 31;
        const float* plane = (p == 0) ? pxy : ((p == 1) ? pxz : pyz);
        int ax = (p == 2) ? 1 : 0;
        int ay = (p == 0) ? 1 : 2;
        s_codes[c][code] = bilerp_border(plane, ch, s_ts[c][ax], s_ts[c][ay]);
    }
    __syncthreads();

    // Layer 1: codes(96) @ w1(96,128) + b1 -> silu. One hidden unit per thread, 8 cams.
    {
        float acc[CPB];
        float bv = __ldg(b1 + tid);
        #pragma unroll
        for (int c = 0; c < CPB; c++) acc[c] = bv;
        for (int k = 0; k < 96; k++) {
            float w = __ldg(w1 + k * HIDDEN + tid);
            #pragma unroll
            for (int c = 0; c < CPB; c++) acc[c] = fmaf(s_codes[c][k], w, acc[c]);
        }
        #pragma unroll
        for (int c = 0; c < CPB; c++) s_h1[c][tid] = silu_f(acc[c]);
    }
    __syncthreads();

    // Layer 2: h1(128) @ w2(128,128) + b2 -> silu
    {
        float acc[CPB];
        float bv = __ldg(b2 + tid);
        #pragma unroll
        for (int c = 0; c < CPB; c++) acc[c] = bv;
        for (int k = 0; k < HIDDEN; k++) {
            float w = __ldg(w2 + k * HIDDEN + tid);
            #pragma unroll
            for (int c = 0; c < CPB; c++) acc[c] = fmaf(s_h1[c][k], w, acc[c]);
        }
        #pragma unroll
        for (int c = 0; c < CPB; c++) s_h2[c][tid] = silu_f(acc[c]);
    }
    __syncthreads();

    // Layer 3: h2(128) @ w3(128,3) + b3, scaled by ALPHA. 24 outputs.
    if (tid < CPB * 3) {
        int c = tid / 3, m = tid % 3;
        float acc = __ldg(b3 + m);
        for (int k = 0; k < HIDDEN; k++)
            acc = fmaf(s_h2[c][k], __ldg(w3 + k * 3 + m), acc);
        s_rot[c][m] = acc * ALPHA;
    }
    __syncthreads();

    // Rodrigues + [R|t;0 0 0 1] @ init_c2w, one camera per thread (8 active).
    if (tid < CPB) {
        int cam = cam0 + tid;
        if (cam < num_cams) {
            float rx = s_rot[tid][0], ry = s_rot[tid][1], rz = s_rot[tid][2];
            float th2 = rx * rx + ry * ry + rz * rz;
            float th = sqrtf(th2);
            float A = sinf(th) / (th + 1e-10f);
            float B = (1.0f - cosf(th)) / (th2 + 1e-10f);
            // R = I + A*K + B*K^2, K = skew(r)
            float R00 = 1.0f - B * (ry * ry + rz * rz);
            float R01 = -A * rz + B * (rx * ry);
            float R02 =  A * ry + B * (rx * rz);
            float R10 =  A * rz + B * (rx * ry);
            float R11 = 1.0f - B * (rx * rx + rz * rz);
            float R12 = -A * rx + B * (ry * rz);
            float R20 = -A * ry + B * (rx * rz);
            float R21 =  A * rx + B * (ry * rz);
            float R22 = 1.0f - B * (rx * rx + ry * ry);

            float tx = s_ts[tid][0], ty = s_ts[tid][1], tz = s_ts[tid][2];
            float C[3][4] = {
                {R00, R01, R02, tx},
                {R10, R11, R12, ty},
                {R20, R21, R22, tz}
            };
            const float* M = init_c2w + (size_t)cam * 16;
            float* o = (float*)(g_table + cam * 4);
            #pragma unroll
            for (int i = 0; i < 3; i++) {
                #pragma unroll
                for (int j = 0; j < 4; j++) {
                    o[i * 4 + j] = C[i][0] * __ldg(M + j)
                                 + C[i][1] * __ldg(M + 4 + j)
                                 + C[i][2] * __ldg(M + 8 + j)
                                 + C[i][3] * __ldg(M + 12 + j);
                }
            }
            // bottom row [0,0,0,1] @ M = M's last row
            o[12] = __ldg(M + 12);
            o[13] = __ldg(M + 13);
            o[14] = __ldg(M + 14);
            o[15] = __ldg(M + 15);
        }
    }
}

// Scatter: out[ray] = table[cam_id[ray]], 4 threads per ray, one float4 each.
__global__ void __launch_bounds__(256) scatter_kernel(
    const int* __restrict__ cam_id,
    float4* __restrict__ out,
    int n_rays)
{
    int idx = blockIdx.x * 256 + threadIdx.x;
    if (idx >= n_rays * 4) return;
    int ray = idx >> 2;
    int part = idx & 3;
    int cid = __ldg(cam_id + ray);
    out[idx] = __ldg(&g_table[cid * 4 + part]);
}

extern "C" void kernel_launch(void* const* d_in, const int* in_sizes, int n_in,
                              void* d_out, int out_size) {
    const int*   cam_id   = (const int*)d_in[0];
    const float* t        = (const float*)d_in[1];
    const float* pxy      = (const float*)d_in[2];
    const float* pxz      = (const float*)d_in[3];
    const float* pyz      = (const float*)d_in[4];
    const float* w1       = (const float*)d_in[5];
    const float* b1       = (const float*)d_in[6];
    const float* w2       = (const float*)d_in[7];
    const float* b2       = (const float*)d_in[8];
    const float* w3       = (const float*)d_in[9];
    const float* b3       = (const float*)d_in[10];
    const float* init_c2w = (const float*)d_in[11];

    int n_rays = in_sizes[0];
    int num_cams = in_sizes[1] / 3;
    if (num_cams > MAX_CAMS) num_cams = MAX_CAMS;

    int nblk1 = (num_cams + CPB - 1) / CPB;
    cam_kernel<<<nblk1, 128>>>(t, pxy, pxz, pyz, w1, b1, w2, b2, w3, b3,
                               init_c2w, num_cams);

    int total = n_rays * 4;
    int nblk2 = (total + 255) / 256;
    scatter_kernel<<<nblk2, 256>>>(cam_id, (float4*)d_out, n_rays);
}